// round 1
// baseline (speedup 1.0000x reference)
#include <cuda_runtime.h>
#include <cstdint>

// Problem shape (fixed by setup_inputs)
#define NPTS   8192      // num_points (both ref and query)
#define NFEAT  256       // num_feat
#define SPLITS 4         // reference-dim splits for occupancy
#define CHUNK  (NPTS / SPLITS)   // 2048 refs per block -> 32KB smem as float4

// Scratch: packed (ordered_d2_bits << 32) | ref_index, min-combined across splits.
__device__ unsigned long long g_best[NPTS];

__global__ void init_best_kernel() {
    int i = blockIdx.x * blockDim.x + threadIdx.x;
    if (i < NPTS) g_best[i] = 0xFFFFFFFFFFFFFFFFull;
}

// Map float to a monotonically ordered uint (total order == float order).
__device__ __forceinline__ unsigned int float_order(float f) {
    unsigned int u = __float_as_uint(f);
    return (u & 0x80000000u) ? ~u : (u | 0x80000000u);
}

// grid(NPTS/128, SPLITS), block(128). Each thread owns one query point and
// scans CHUNK reference points held in shared memory as float4{x,y,z,|r|^2}.
// argmin_i (|r_i|^2 - 2 q.r_i) == argmin_i d2(i, q).
__global__ void __launch_bounds__(128) nn_argmin_kernel(
    const float* __restrict__ t1,   // refs  [3, NPTS]
    const float* __restrict__ t2)   // query [3, NPTS]
{
    __shared__ float4 refs[CHUNK];
    const int base = blockIdx.y * CHUNK;

    // Cooperative load of this block's reference chunk (coalesced).
    for (int r = threadIdx.x; r < CHUNK; r += 128) {
        float x = t1[base + r];
        float y = t1[NPTS + base + r];
        float z = t1[2 * NPTS + base + r];
        refs[r] = make_float4(x, y, z, fmaf(x, x, fmaf(y, y, z * z)));
    }
    __syncthreads();

    const int q = blockIdx.x * 128 + threadIdx.x;
    const float a = -2.0f * t2[q];
    const float b = -2.0f * t2[NPTS + q];
    const float c = -2.0f * t2[2 * NPTS + q];

    // 4 rotating partial minima to break the loop-carried min dependency.
    float best[4] = {3.4e38f, 3.4e38f, 3.4e38f, 3.4e38f};
    int   bidx[4] = {0, 0, 0, 0};

    #pragma unroll 4
    for (int r = 0; r < CHUNK; r += 4) {
        #pragma unroll
        for (int u = 0; u < 4; ++u) {
            float4 f = refs[r + u];
            float v = fmaf(a, f.x, fmaf(b, f.y, fmaf(c, f.z, f.w)));
            if (v < best[u]) { best[u] = v; bidx[u] = base + r + u; }
        }
    }

    // Combine partials into a packed key; ties resolve to the lowest index,
    // matching jnp.argmin semantics.
    unsigned long long key = 0xFFFFFFFFFFFFFFFFull;
    #pragma unroll
    for (int u = 0; u < 4; ++u) {
        unsigned long long k =
            ((unsigned long long)float_order(best[u]) << 32) |
            (unsigned int)bidx[u];
        key = (k < key) ? k : key;
    }
    atomicMin(&g_best[q], key);
}

// grid(NPTS/256, 512/ROWS), block(256).
// Rows [0,256): out[f][j] = emb1[f][ind[j]]  (gather, L2-resident emb1)
// Rows [256,512): out[f][j] = emb2[f-256][j] (straight copy)
#define GROWS 16
__global__ void __launch_bounds__(256) gather_concat_kernel(
    const float* __restrict__ emb1,
    const float* __restrict__ emb2,
    float* __restrict__ out)
{
    __shared__ int inds[256];
    const int j0  = blockIdx.x * 256;
    const int tid = threadIdx.x;
    inds[tid] = (int)(unsigned int)(g_best[j0 + tid] & 0xFFFFFFFFull);
    __syncthreads();

    const int j  = j0 + tid;
    const int f0 = blockIdx.y * GROWS;

    if (f0 < NFEAT) {
        const int ind = inds[tid];
        #pragma unroll
        for (int r = 0; r < GROWS; ++r) {
            int f = f0 + r;
            out[(size_t)f * NPTS + j] = emb1[(size_t)f * NPTS + ind];
        }
    } else {
        #pragma unroll
        for (int r = 0; r < GROWS; ++r) {
            int f = f0 + r;
            out[(size_t)f * NPTS + j] = emb2[(size_t)(f - NFEAT) * NPTS + j];
        }
    }
}

extern "C" void kernel_launch(void* const* d_in, const int* in_sizes, int n_in,
                              void* d_out, int out_size) {
    const float* emb1 = (const float*)d_in[0];
    const float* emb2 = (const float*)d_in[1];
    const float* t1   = (const float*)d_in[2];
    const float* t2   = (const float*)d_in[3];
    float* out = (float*)d_out;

    init_best_kernel<<<NPTS / 256, 256>>>();

    dim3 nn_grid(NPTS / 128, SPLITS);
    nn_argmin_kernel<<<nn_grid, 128>>>(t1, t2);

    dim3 g_grid(NPTS / 256, (2 * NFEAT) / GROWS);
    gather_concat_kernel<<<g_grid, 256>>>(emb1, emb2, out);
}